// round 13
// baseline (speedup 1.0000x reference)
#include <cuda_runtime.h>
#include <cuda_bf16.h>
#include <cstdint>

// ---------------------------------------------------------------------------
// StressGNN: 2-layer GCN + mean readout + FC.
//   k_build (one-pass bucket CSR) -> k_dinv_g0 ->
//   [agg1+gemm1 fused, 4-lane groups (R6 champion), fp32 g1 out] ->
//   agg2 (warp/node, ISSUE-optimized: fp32 g1 + packed f32x2 accumulate,
//         ~4 warp-issues/edge instead of ~7) ->
//   [gemm2(FFMA2) + relu + Wfc-dot + reduce + fused final]
// agg2 measured ISSUE-bound (issue 56%, alu 34%, mem idle) => optimize
// instructions/edge, not bytes.
// Self-resetting device state => graph-replay deterministic.
// tcgen05 unavailable (harness lowers to .target sm_103, no 'a').
// ---------------------------------------------------------------------------

#define N_MAX 100000
#define E_MAX 1600000
#define CAP   96          // bucket capacity; P(deg>96)~1e-40 for Poisson(16)

__device__ int    g_deg[N_MAX];              // edge count (zeroed each cycle)
__device__ int    g_cnt[N_MAX];              // snapshot: in-edges per node
__device__ int    g_colb[N_MAX * CAP];       // bucketed src indices (38.4 MB)
__device__ float  g_dinv[N_MAX];             // (cnt+1)^-1/2
__device__ float2 g_g0[4 * N_MAX];           // dinv[i]*x[i]             [N,8]
__device__ float2 g_g1f[32 * N_MAX];         // dinv[i]*relu(a1@W1+b1)   [N,64] fp32
__device__ float4 g_a2[16 * N_MAX];          // layer-2 aggregated input [N,64]
__device__ int    g_done;
__device__ float  g_total;

#define PACKED_ONE 0x3F8000003F800000ULL     // {1.0f, 1.0f}

// ---------------------------------------------------------------------------
// ONE pass: histogram + direct bucket scatter (no rank array, no scan).
__global__ void k_build(const int* __restrict__ ei, int E) {
    int e = blockIdx.x * blockDim.x + threadIdx.x;
    if (e >= E) return;
    int s = ei[e];
    int d = ei[E + e];
    int pos = atomicAdd(&g_deg[d], 1);       // deg starts at 0 every replay
    if (pos < CAP) g_colb[d * CAP + pos] = s;
}

// deg snapshot + self-reset + dinv + g0
__global__ void k_dinv_g0(const float* __restrict__ x, int n) {
    int i = blockIdx.x * blockDim.x + threadIdx.x;
    if (i >= n) return;
    int c = g_deg[i];
    g_deg[i] = 0;                            // self-reset for next replay
    g_cnt[i] = (c < CAP) ? c : CAP;
    float di = rsqrtf((float)(c + 1));       // +1 self loop
    g_dinv[i] = di;
    const float4* x4 = (const float4*)x;
    float4 v0 = x4[2 * i], v1 = x4[2 * i + 1];
    g_g0[4 * i]     = make_float2(di * v0.x, di * v0.y);
    g_g0[4 * i + 1] = make_float2(di * v0.z, di * v0.w);
    g_g0[4 * i + 2] = make_float2(di * v1.x, di * v1.y);
    g_g0[4 * i + 3] = make_float2(di * v1.z, di * v1.w);
}

// ---------------------------------------------------------------------------
// Fused layer 1 (R6 champion): 4 lanes/node; lane owns 2 features during
// aggregation; shfl(width=4) reassembles; lane emits 16 of 64 outputs (fp32).
__global__ void __launch_bounds__(256)
k_agg1_gemm1(const float* __restrict__ W1, const float* __restrict__ b1, int n) {
    __shared__ float W1s[8 * 64];
    __shared__ float b1s[64];
    int tid = threadIdx.x;
    for (int t = tid; t < 512; t += blockDim.x) W1s[t] = W1[t];
    if (tid < 64) b1s[tid] = b1[tid];
    __syncthreads();

    int gtid = blockIdx.x * blockDim.x + tid;
    int node = gtid >> 2;
    int sub  = gtid & 3;
    if (node >= n) return;

    float2 acc0 = g_g0[4 * node + sub];      // self loop
    float2 acc1 = make_float2(0.f, 0.f);
    int cnt = g_cnt[node];
    const int* col = &g_colb[node * CAP];
    int j = 0;
    for (; j + 4 <= cnt; j += 4) {
        int s0 = col[j], s1 = col[j + 1], s2 = col[j + 2], s3 = col[j + 3];
        float2 v0 = g_g0[4 * s0 + sub];
        float2 v1 = g_g0[4 * s1 + sub];
        float2 v2 = g_g0[4 * s2 + sub];
        float2 v3 = g_g0[4 * s3 + sub];
        acc0.x += v0.x; acc0.y += v0.y;
        acc1.x += v1.x; acc1.y += v1.y;
        acc0.x += v2.x; acc0.y += v2.y;
        acc1.x += v3.x; acc1.y += v3.y;
    }
    for (; j < cnt; j++) {
        int s = col[j];
        float2 v = g_g0[4 * s + sub];
        acc0.x += v.x; acc0.y += v.y;
    }
    float di = g_dinv[node];
    float mx = di * (acc0.x + acc1.x);
    float my = di * (acc0.y + acc1.y);

    float a[8];
#pragma unroll
    for (int g = 0; g < 4; g++) {
        a[2 * g]     = __shfl_sync(0xffffffffu, mx, g, 4);
        a[2 * g + 1] = __shfl_sync(0xffffffffu, my, g, 4);
    }

    int cbase = sub * 16;
    float r[16];
#pragma unroll
    for (int c = 0; c < 16; c++) r[c] = b1s[cbase + c];
#pragma unroll
    for (int k = 0; k < 8; k++) {
        float ak = a[k];
        const float* wr = &W1s[k * 64 + cbase];
#pragma unroll
        for (int c = 0; c < 16; c++) r[c] += ak * wr[c];
    }
    // fp32 out: this lane writes 64B contiguous; group covers the 256B row
    float4* dst = (float4*)&g_g1f[node * 32 + sub * 8];
#pragma unroll
    for (int q = 0; q < 4; q++)
        dst[q] = make_float4(di * fmaxf(r[4 * q],     0.f),
                             di * fmaxf(r[4 * q + 1], 0.f),
                             di * fmaxf(r[4 * q + 2], 0.f),
                             di * fmaxf(r[4 * q + 3], 0.f));
}

// ---------------------------------------------------------------------------
// agg2: warp/node, ISSUE-optimized. Per edge: idx LDG + data LDG.64 +
// IMAD.WIDE + ONE packed fma.rn.f32x2 (acc += v*1). 4 accumulator chains.
__global__ void k_agg2(int n) {
    int gtid = blockIdx.x * blockDim.x + threadIdx.x;
    int node = gtid >> 5;
    int lane = gtid & 31;
    if (node >= n) return;
    const unsigned long long* g1 = (const unsigned long long*)g_g1f;
    unsigned long long acc0 = g1[(size_t)node * 32 + lane];     // self loop
    unsigned long long acc1 = 0ull, acc2 = 0ull, acc3 = 0ull;
    int cnt = g_cnt[node];
    const int* col = &g_colb[node * CAP];
    int j = 0;
    for (; j + 8 <= cnt; j += 8) {
        int s0 = col[j],     s1 = col[j + 1], s2 = col[j + 2], s3 = col[j + 3];
        int s4 = col[j + 4], s5 = col[j + 5], s6 = col[j + 6], s7 = col[j + 7];
        unsigned long long v0 = g1[(size_t)s0 * 32 + lane];
        unsigned long long v1 = g1[(size_t)s1 * 32 + lane];
        unsigned long long v2 = g1[(size_t)s2 * 32 + lane];
        unsigned long long v3 = g1[(size_t)s3 * 32 + lane];
        unsigned long long v4 = g1[(size_t)s4 * 32 + lane];
        unsigned long long v5 = g1[(size_t)s5 * 32 + lane];
        unsigned long long v6 = g1[(size_t)s6 * 32 + lane];
        unsigned long long v7 = g1[(size_t)s7 * 32 + lane];
        asm("fma.rn.f32x2 %0, %1, %2, %0;" : "+l"(acc0) : "l"(v0), "l"(PACKED_ONE));
        asm("fma.rn.f32x2 %0, %1, %2, %0;" : "+l"(acc1) : "l"(v1), "l"(PACKED_ONE));
        asm("fma.rn.f32x2 %0, %1, %2, %0;" : "+l"(acc2) : "l"(v2), "l"(PACKED_ONE));
        asm("fma.rn.f32x2 %0, %1, %2, %0;" : "+l"(acc3) : "l"(v3), "l"(PACKED_ONE));
        asm("fma.rn.f32x2 %0, %1, %2, %0;" : "+l"(acc0) : "l"(v4), "l"(PACKED_ONE));
        asm("fma.rn.f32x2 %0, %1, %2, %0;" : "+l"(acc1) : "l"(v5), "l"(PACKED_ONE));
        asm("fma.rn.f32x2 %0, %1, %2, %0;" : "+l"(acc2) : "l"(v6), "l"(PACKED_ONE));
        asm("fma.rn.f32x2 %0, %1, %2, %0;" : "+l"(acc3) : "l"(v7), "l"(PACKED_ONE));
    }
    if (j + 4 <= cnt) {
        int s0 = col[j], s1 = col[j + 1], s2 = col[j + 2], s3 = col[j + 3];
        unsigned long long v0 = g1[(size_t)s0 * 32 + lane];
        unsigned long long v1 = g1[(size_t)s1 * 32 + lane];
        unsigned long long v2 = g1[(size_t)s2 * 32 + lane];
        unsigned long long v3 = g1[(size_t)s3 * 32 + lane];
        asm("fma.rn.f32x2 %0, %1, %2, %0;" : "+l"(acc0) : "l"(v0), "l"(PACKED_ONE));
        asm("fma.rn.f32x2 %0, %1, %2, %0;" : "+l"(acc1) : "l"(v1), "l"(PACKED_ONE));
        asm("fma.rn.f32x2 %0, %1, %2, %0;" : "+l"(acc2) : "l"(v2), "l"(PACKED_ONE));
        asm("fma.rn.f32x2 %0, %1, %2, %0;" : "+l"(acc3) : "l"(v3), "l"(PACKED_ONE));
        j += 4;
    }
    for (; j < cnt; j++) {
        int s = col[j];
        unsigned long long v = g1[(size_t)s * 32 + lane];
        asm("fma.rn.f32x2 %0, %1, %2, %0;" : "+l"(acc0) : "l"(v), "l"(PACKED_ONE));
    }
    // combine chains (packed adds)
    asm("fma.rn.f32x2 %0, %1, %2, %0;" : "+l"(acc0) : "l"(acc1), "l"(PACKED_ONE));
    asm("fma.rn.f32x2 %0, %1, %2, %0;" : "+l"(acc2) : "l"(acc3), "l"(PACKED_ONE));
    asm("fma.rn.f32x2 %0, %1, %2, %0;" : "+l"(acc0) : "l"(acc2), "l"(PACKED_ONE));
    unsigned int lo, hi;
    asm("mov.b64 {%0, %1}, %2;" : "=r"(lo), "=r"(hi) : "l"(acc0));
    float di = g_dinv[node];
    ((float2*)g_a2)[node * 32 + lane] =
        make_float2(di * __uint_as_float(lo), di * __uint_as_float(hi));
}

// ---------------------------------------------------------------------------
// gemm2 + relu + Wfc dot + block reduction + fused final output (ticket).
__global__ void __launch_bounds__(256)
k_gemm2_reduce(const float* __restrict__ W2, const float* __restrict__ b2,
               const float* __restrict__ Wfc, const float* __restrict__ bfc,
               float* __restrict__ out, float invn, int n) {
    __shared__ float W2s[64 * 128];
    __shared__ float b2s[128];
    __shared__ float wfs[128];
    __shared__ float red[256];
    int tid = threadIdx.x;
    for (int t = tid; t < 2048; t += blockDim.x)
        ((float4*)W2s)[t] = ((const float4*)W2)[t];
    if (tid < 128) { b2s[tid] = b2[tid]; wfs[tid] = Wfc[tid]; }
    __syncthreads();

    int i = blockIdx.x * blockDim.x + tid;
    float nodesum = 0.0f;
    if (i < n) {
        float a[64];
        const float4* ar = &g_a2[i * 16];
#pragma unroll
        for (int t = 0; t < 16; t++) {
            float4 v = ar[t];
            a[4 * t] = v.x; a[4 * t + 1] = v.y; a[4 * t + 2] = v.z; a[4 * t + 3] = v.w;
        }
        for (int ch = 0; ch < 4; ch++) {
            unsigned long long acc[16];
#pragma unroll
            for (int t = 0; t < 16; t++) acc[t] = 0ull;
#pragma unroll
            for (int k = 0; k < 64; k++) {
                unsigned int au = __float_as_uint(a[k]);
                unsigned long long ap;
                asm("mov.b64 %0, {%1, %1};" : "=l"(ap) : "r"(au));
                const ulonglong2* w =
                    reinterpret_cast<const ulonglong2*>(&W2s[k * 128 + ch * 32]);
#pragma unroll
                for (int t = 0; t < 8; t++) {
                    ulonglong2 wv = w[t];
                    asm("fma.rn.f32x2 %0, %1, %2, %0;"
                        : "+l"(acc[2 * t]) : "l"(ap), "l"(wv.x));
                    asm("fma.rn.f32x2 %0, %1, %2, %0;"
                        : "+l"(acc[2 * t + 1]) : "l"(ap), "l"(wv.y));
                }
            }
#pragma unroll
            for (int u = 0; u < 16; u++) {
                unsigned int lo_u, hi_u;
                asm("mov.b64 {%0, %1}, %2;" : "=r"(lo_u), "=r"(hi_u) : "l"(acc[u]));
                int c = ch * 32 + 2 * u;
                float v0 = fmaxf(__uint_as_float(lo_u) + b2s[c], 0.0f);
                float v1 = fmaxf(__uint_as_float(hi_u) + b2s[c + 1], 0.0f);
                nodesum += v0 * wfs[c] + v1 * wfs[c + 1];
            }
        }
    }
    red[tid] = nodesum;
    __syncthreads();
    for (int off = 128; off > 0; off >>= 1) {
        if (tid < off) red[tid] += red[tid + off];
        __syncthreads();
    }
    if (tid == 0) {
        atomicAdd(&g_total, red[0]);
        __threadfence();
        int ticket = atomicAdd(&g_done, 1);
        if (ticket == (int)gridDim.x - 1) {           // last block finalizes
            float tot = atomicExch(&g_total, 0.0f);   // read + self-reset
            out[0] = tot * invn + bfc[0];
            g_done = 0;                               // self-reset
        }
    }
}

// ---------------------------------------------------------------------------
extern "C" void kernel_launch(void* const* d_in, const int* in_sizes, int n_in,
                              void* d_out, int out_size) {
    const float* x   = (const float*)d_in[0];
    const int*   ei  = (const int*)  d_in[1];
    const float* W1  = (const float*)d_in[2];
    const float* b1  = (const float*)d_in[3];
    const float* W2  = (const float*)d_in[4];
    const float* b2  = (const float*)d_in[5];
    const float* Wfc = (const float*)d_in[6];
    const float* bfc = (const float*)d_in[7];

    int n = in_sizes[0] / 8;
    int E = in_sizes[1] / 2;
    if (n > N_MAX) n = N_MAX;
    if (E > E_MAX) E = E_MAX;

    int nb = (n + 255) / 256;
    int eb = (E + 255) / 256;
    int qb = (n * 4 + 255) / 256;    // 4 lanes per node (agg1)
    int wb = (n * 32 + 255) / 256;   // warp per node (agg2)

    k_build       <<<eb, 256>>>(ei, E);      // launch 0
    k_dinv_g0     <<<nb, 256>>>(x, n);       // launch 1
    k_agg1_gemm1  <<<qb, 256>>>(W1, b1, n);  // launch 2
    k_agg2        <<<wb, 256>>>(n);          // launch 3  <- profiled slot
    k_gemm2_reduce<<<nb, 256>>>(W2, b2, Wfc, bfc, (float*)d_out,
                                1.0f / (float)n, n);
}

// round 14
// speedup vs baseline: 1.0551x; 1.0551x over previous
#include <cuda_runtime.h>
#include <cuda_bf16.h>
#include <cstdint>

// ---------------------------------------------------------------------------
// StressGNN: 2-layer GCN + mean readout + FC.
//   k_build (one-pass bucket CSR) -> k_dinv_g0 ->
//   [agg1+gemm1 fused, 4-lane groups (R6 champion), bf16 g1 out] ->
//   agg2 (warp/node, bf16 rows = 1 line/edge, packed add.rn.bf16x2
//         accumulate = ~4 warp-issues/edge; fp32 only at chain combine) ->
//   [gemm2(FFMA2) + relu + Wfc-dot + reduce + fused final]
// agg2 is balanced issue/wavefront-bound: cut instructions per edge WITHOUT
// adding bytes (R13 lesson: fp32 rows doubled wavefronts and regressed).
// Self-resetting device state => graph-replay deterministic.
// tcgen05 unavailable (harness lowers to .target sm_103, no 'a').
// ---------------------------------------------------------------------------

#define N_MAX 100000
#define E_MAX 1600000
#define CAP   96          // bucket capacity; P(deg>96)~1e-40 for Poisson(16)

__device__ int    g_deg[N_MAX];              // edge count (zeroed each cycle)
__device__ int    g_cnt[N_MAX];              // snapshot: in-edges per node
__device__ int    g_colb[N_MAX * CAP];       // bucketed src indices (38.4 MB)
__device__ float  g_dinv[N_MAX];             // (cnt+1)^-1/2
__device__ float2 g_g0[4 * N_MAX];           // dinv[i]*x[i]             [N,8]
__device__ __nv_bfloat162 g_g1b[32 * N_MAX]; // dinv[i]*relu(a1@W1+b1)   [N,64] bf16
__device__ float4 g_a2[16 * N_MAX];          // layer-2 aggregated input [N,64]
__device__ int    g_done;
__device__ float  g_total;

// ---------------------------------------------------------------------------
// ONE pass: histogram + direct bucket scatter (no rank array, no scan).
__global__ void k_build(const int* __restrict__ ei, int E) {
    int e = blockIdx.x * blockDim.x + threadIdx.x;
    if (e >= E) return;
    int s = ei[e];
    int d = ei[E + e];
    int pos = atomicAdd(&g_deg[d], 1);       // deg starts at 0 every replay
    if (pos < CAP) g_colb[d * CAP + pos] = s;
}

// deg snapshot + self-reset + dinv + g0
__global__ void k_dinv_g0(const float* __restrict__ x, int n) {
    int i = blockIdx.x * blockDim.x + threadIdx.x;
    if (i >= n) return;
    int c = g_deg[i];
    g_deg[i] = 0;                            // self-reset for next replay
    g_cnt[i] = (c < CAP) ? c : CAP;
    float di = rsqrtf((float)(c + 1));       // +1 self loop
    g_dinv[i] = di;
    const float4* x4 = (const float4*)x;
    float4 v0 = x4[2 * i], v1 = x4[2 * i + 1];
    g_g0[4 * i]     = make_float2(di * v0.x, di * v0.y);
    g_g0[4 * i + 1] = make_float2(di * v0.z, di * v0.w);
    g_g0[4 * i + 2] = make_float2(di * v1.x, di * v1.y);
    g_g0[4 * i + 3] = make_float2(di * v1.z, di * v1.w);
}

// ---------------------------------------------------------------------------
// Fused layer 1 (R6 champion): 4 lanes/node; lane owns 2 features during
// aggregation; shfl(width=4) reassembles; lane emits 16 of 64 outputs (bf16).
__global__ void __launch_bounds__(256)
k_agg1_gemm1(const float* __restrict__ W1, const float* __restrict__ b1, int n) {
    __shared__ float W1s[8 * 64];
    __shared__ float b1s[64];
    int tid = threadIdx.x;
    for (int t = tid; t < 512; t += blockDim.x) W1s[t] = W1[t];
    if (tid < 64) b1s[tid] = b1[tid];
    __syncthreads();

    int gtid = blockIdx.x * blockDim.x + tid;
    int node = gtid >> 2;
    int sub  = gtid & 3;
    if (node >= n) return;

    float2 acc0 = g_g0[4 * node + sub];      // self loop
    float2 acc1 = make_float2(0.f, 0.f);
    int cnt = g_cnt[node];
    const int* col = &g_colb[node * CAP];
    int j = 0;
    for (; j + 4 <= cnt; j += 4) {
        int s0 = col[j], s1 = col[j + 1], s2 = col[j + 2], s3 = col[j + 3];
        float2 v0 = g_g0[4 * s0 + sub];
        float2 v1 = g_g0[4 * s1 + sub];
        float2 v2 = g_g0[4 * s2 + sub];
        float2 v3 = g_g0[4 * s3 + sub];
        acc0.x += v0.x; acc0.y += v0.y;
        acc1.x += v1.x; acc1.y += v1.y;
        acc0.x += v2.x; acc0.y += v2.y;
        acc1.x += v3.x; acc1.y += v3.y;
    }
    for (; j < cnt; j++) {
        int s = col[j];
        float2 v = g_g0[4 * s + sub];
        acc0.x += v.x; acc0.y += v.y;
    }
    float di = g_dinv[node];
    float mx = di * (acc0.x + acc1.x);
    float my = di * (acc0.y + acc1.y);

    float a[8];
#pragma unroll
    for (int g = 0; g < 4; g++) {
        a[2 * g]     = __shfl_sync(0xffffffffu, mx, g, 4);
        a[2 * g + 1] = __shfl_sync(0xffffffffu, my, g, 4);
    }

    int cbase = sub * 16;
    float r[16];
#pragma unroll
    for (int c = 0; c < 16; c++) r[c] = b1s[cbase + c];
#pragma unroll
    for (int k = 0; k < 8; k++) {
        float ak = a[k];
        const float* wr = &W1s[k * 64 + cbase];
#pragma unroll
        for (int c = 0; c < 16; c++) r[c] += ak * wr[c];
    }
    __nv_bfloat162 ob[8];
#pragma unroll
    for (int t = 0; t < 8; t++)
        ob[t] = __float22bfloat162_rn(make_float2(di * fmaxf(r[2 * t], 0.f),
                                                  di * fmaxf(r[2 * t + 1], 0.f)));
    uint4* dst = (uint4*)&g_g1b[node * 32 + sub * 8];
    dst[0] = *reinterpret_cast<uint4*>(&ob[0]);
    dst[1] = *reinterpret_cast<uint4*>(&ob[4]);
}

// ---------------------------------------------------------------------------
// agg2: warp/node. bf16 rows (1 L1 line/edge, same as R12 champion) +
// packed add.rn.bf16x2 accumulation (1 issue/edge instead of cvt+2 FADD).
// 4 short chains; fp32 conversion only at chain combine.
__global__ void k_agg2(int n) {
    int gtid = blockIdx.x * blockDim.x + threadIdx.x;
    int node = gtid >> 5;
    int lane = gtid & 31;
    if (node >= n) return;
    const uint32_t* g1 = (const uint32_t*)g_g1b;
    uint32_t acc0 = g1[(size_t)node * 32 + lane];    // self loop (raw bf16x2)
    uint32_t acc1 = 0u, acc2 = 0u, acc3 = 0u;        // bf16x2 {+0,+0}
    int cnt = g_cnt[node];
    const int* col = &g_colb[node * CAP];
    int j = 0;
    for (; j + 8 <= cnt; j += 8) {
        int s0 = col[j],     s1 = col[j + 1], s2 = col[j + 2], s3 = col[j + 3];
        int s4 = col[j + 4], s5 = col[j + 5], s6 = col[j + 6], s7 = col[j + 7];
        uint32_t v0 = g1[(size_t)s0 * 32 + lane];
        uint32_t v1 = g1[(size_t)s1 * 32 + lane];
        uint32_t v2 = g1[(size_t)s2 * 32 + lane];
        uint32_t v3 = g1[(size_t)s3 * 32 + lane];
        uint32_t v4 = g1[(size_t)s4 * 32 + lane];
        uint32_t v5 = g1[(size_t)s5 * 32 + lane];
        uint32_t v6 = g1[(size_t)s6 * 32 + lane];
        uint32_t v7 = g1[(size_t)s7 * 32 + lane];
        asm("add.rn.bf16x2 %0, %0, %1;" : "+r"(acc0) : "r"(v0));
        asm("add.rn.bf16x2 %0, %0, %1;" : "+r"(acc1) : "r"(v1));
        asm("add.rn.bf16x2 %0, %0, %1;" : "+r"(acc2) : "r"(v2));
        asm("add.rn.bf16x2 %0, %0, %1;" : "+r"(acc3) : "r"(v3));
        asm("add.rn.bf16x2 %0, %0, %1;" : "+r"(acc0) : "r"(v4));
        asm("add.rn.bf16x2 %0, %0, %1;" : "+r"(acc1) : "r"(v5));
        asm("add.rn.bf16x2 %0, %0, %1;" : "+r"(acc2) : "r"(v6));
        asm("add.rn.bf16x2 %0, %0, %1;" : "+r"(acc3) : "r"(v7));
    }
    if (j + 4 <= cnt) {
        int s0 = col[j], s1 = col[j + 1], s2 = col[j + 2], s3 = col[j + 3];
        uint32_t v0 = g1[(size_t)s0 * 32 + lane];
        uint32_t v1 = g1[(size_t)s1 * 32 + lane];
        uint32_t v2 = g1[(size_t)s2 * 32 + lane];
        uint32_t v3 = g1[(size_t)s3 * 32 + lane];
        asm("add.rn.bf16x2 %0, %0, %1;" : "+r"(acc0) : "r"(v0));
        asm("add.rn.bf16x2 %0, %0, %1;" : "+r"(acc1) : "r"(v1));
        asm("add.rn.bf16x2 %0, %0, %1;" : "+r"(acc2) : "r"(v2));
        asm("add.rn.bf16x2 %0, %0, %1;" : "+r"(acc3) : "r"(v3));
        j += 4;
    }
    for (; j < cnt; j++) {
        int s = col[j];
        uint32_t v = g1[(size_t)s * 32 + lane];
        asm("add.rn.bf16x2 %0, %0, %1;" : "+r"(acc0) : "r"(v));
    }
    // combine chains in fp32 (precise), scale by dinv, store fp32 a2
    float2 f0 = __bfloat1622float2(*reinterpret_cast<__nv_bfloat162*>(&acc0));
    float2 f1 = __bfloat1622float2(*reinterpret_cast<__nv_bfloat162*>(&acc1));
    float2 f2 = __bfloat1622float2(*reinterpret_cast<__nv_bfloat162*>(&acc2));
    float2 f3 = __bfloat1622float2(*reinterpret_cast<__nv_bfloat162*>(&acc3));
    float di = g_dinv[node];
    ((float2*)g_a2)[node * 32 + lane] =
        make_float2(di * ((f0.x + f1.x) + (f2.x + f3.x)),
                    di * ((f0.y + f1.y) + (f2.y + f3.y)));
}

// ---------------------------------------------------------------------------
// gemm2 + relu + Wfc dot + block reduction + fused final output (ticket).
__global__ void __launch_bounds__(256)
k_gemm2_reduce(const float* __restrict__ W2, const float* __restrict__ b2,
               const float* __restrict__ Wfc, const float* __restrict__ bfc,
               float* __restrict__ out, float invn, int n) {
    __shared__ float W2s[64 * 128];
    __shared__ float b2s[128];
    __shared__ float wfs[128];
    __shared__ float red[256];
    int tid = threadIdx.x;
    for (int t = tid; t < 2048; t += blockDim.x)
        ((float4*)W2s)[t] = ((const float4*)W2)[t];
    if (tid < 128) { b2s[tid] = b2[tid]; wfs[tid] = Wfc[tid]; }
    __syncthreads();

    int i = blockIdx.x * blockDim.x + tid;
    float nodesum = 0.0f;
    if (i < n) {
        float a[64];
        const float4* ar = &g_a2[i * 16];
#pragma unroll
        for (int t = 0; t < 16; t++) {
            float4 v = ar[t];
            a[4 * t] = v.x; a[4 * t + 1] = v.y; a[4 * t + 2] = v.z; a[4 * t + 3] = v.w;
        }
        for (int ch = 0; ch < 4; ch++) {
            unsigned long long acc[16];
#pragma unroll
            for (int t = 0; t < 16; t++) acc[t] = 0ull;
#pragma unroll
            for (int k = 0; k < 64; k++) {
                unsigned int au = __float_as_uint(a[k]);
                unsigned long long ap;
                asm("mov.b64 %0, {%1, %1};" : "=l"(ap) : "r"(au));
                const ulonglong2* w =
                    reinterpret_cast<const ulonglong2*>(&W2s[k * 128 + ch * 32]);
#pragma unroll
                for (int t = 0; t < 8; t++) {
                    ulonglong2 wv = w[t];
                    asm("fma.rn.f32x2 %0, %1, %2, %0;"
                        : "+l"(acc[2 * t]) : "l"(ap), "l"(wv.x));
                    asm("fma.rn.f32x2 %0, %1, %2, %0;"
                        : "+l"(acc[2 * t + 1]) : "l"(ap), "l"(wv.y));
                }
            }
#pragma unroll
            for (int u = 0; u < 16; u++) {
                unsigned int lo_u, hi_u;
                asm("mov.b64 {%0, %1}, %2;" : "=r"(lo_u), "=r"(hi_u) : "l"(acc[u]));
                int c = ch * 32 + 2 * u;
                float v0 = fmaxf(__uint_as_float(lo_u) + b2s[c], 0.0f);
                float v1 = fmaxf(__uint_as_float(hi_u) + b2s[c + 1], 0.0f);
                nodesum += v0 * wfs[c] + v1 * wfs[c + 1];
            }
        }
    }
    red[tid] = nodesum;
    __syncthreads();
    for (int off = 128; off > 0; off >>= 1) {
        if (tid < off) red[tid] += red[tid + off];
        __syncthreads();
    }
    if (tid == 0) {
        atomicAdd(&g_total, red[0]);
        __threadfence();
        int ticket = atomicAdd(&g_done, 1);
        if (ticket == (int)gridDim.x - 1) {           // last block finalizes
            float tot = atomicExch(&g_total, 0.0f);   // read + self-reset
            out[0] = tot * invn + bfc[0];
            g_done = 0;                               // self-reset
        }
    }
}

// ---------------------------------------------------------------------------
extern "C" void kernel_launch(void* const* d_in, const int* in_sizes, int n_in,
                              void* d_out, int out_size) {
    const float* x   = (const float*)d_in[0];
    const int*   ei  = (const int*)  d_in[1];
    const float* W1  = (const float*)d_in[2];
    const float* b1  = (const float*)d_in[3];
    const float* W2  = (const float*)d_in[4];
    const float* b2  = (const float*)d_in[5];
    const float* Wfc = (const float*)d_in[6];
    const float* bfc = (const float*)d_in[7];

    int n = in_sizes[0] / 8;
    int E = in_sizes[1] / 2;
    if (n > N_MAX) n = N_MAX;
    if (E > E_MAX) E = E_MAX;

    int nb = (n + 255) / 256;
    int eb = (E + 255) / 256;
    int qb = (n * 4 + 255) / 256;    // 4 lanes per node (agg1)
    int wb = (n * 32 + 255) / 256;   // warp per node (agg2)

    k_build       <<<eb, 256>>>(ei, E);      // launch 0
    k_dinv_g0     <<<nb, 256>>>(x, n);       // launch 1
    k_agg1_gemm1  <<<qb, 256>>>(W1, b1, n);  // launch 2
    k_agg2        <<<wb, 256>>>(n);          // launch 3  <- profiled slot
    k_gemm2_reduce<<<nb, 256>>>(W2, b2, Wfc, bfc, (float*)d_out,
                                1.0f / (float)n, n);
}

// round 15
// speedup vs baseline: 1.0778x; 1.0215x over previous
#include <cuda_runtime.h>
#include <cuda_bf16.h>
#include <cstdint>

// ---------------------------------------------------------------------------
// StressGNN: 2-layer GCN + mean readout + FC.
//   k_build (one-pass bucket CSR) -> k_dinv_g0 ->
//   [agg1+gemm1 fused, 4-lane groups, INT4 index loads (bucket-aligned)] ->
//   agg2 (warp/node, bf16 rows, packed add.rn.bf16x2, INT4 index loads) ->
//   [gemm2(FFMA2) + relu + Wfc-dot + reduce + fused final]
// Buckets start at node*384B (16B-aligned) and unrolled loops step by 4 =>
// every int4 index load is naturally aligned (fixes R11's prologue penalty).
// Self-resetting device state => graph-replay deterministic.
// tcgen05 unavailable (harness lowers to .target sm_103, no 'a').
// ---------------------------------------------------------------------------

#define N_MAX 100000
#define E_MAX 1600000
#define CAP   96          // bucket capacity; P(deg>96)~1e-40 for Poisson(16)

__device__ int    g_deg[N_MAX];              // edge count (zeroed each cycle)
__device__ int    g_cnt[N_MAX];              // snapshot: in-edges per node
__device__ int    g_colb[N_MAX * CAP];       // bucketed src indices (38.4 MB)
__device__ float  g_dinv[N_MAX];             // (cnt+1)^-1/2
__device__ float2 g_g0[4 * N_MAX];           // dinv[i]*x[i]             [N,8]
__device__ __nv_bfloat162 g_g1b[32 * N_MAX]; // dinv[i]*relu(a1@W1+b1)   [N,64] bf16
__device__ float4 g_a2[16 * N_MAX];          // layer-2 aggregated input [N,64]
__device__ int    g_done;
__device__ float  g_total;

// ---------------------------------------------------------------------------
// ONE pass: histogram + direct bucket scatter (no rank array, no scan).
__global__ void k_build(const int* __restrict__ ei, int E) {
    int e = blockIdx.x * blockDim.x + threadIdx.x;
    if (e >= E) return;
    int s = ei[e];
    int d = ei[E + e];
    int pos = atomicAdd(&g_deg[d], 1);       // deg starts at 0 every replay
    if (pos < CAP) g_colb[d * CAP + pos] = s;
}

// deg snapshot + self-reset + dinv + g0
__global__ void k_dinv_g0(const float* __restrict__ x, int n) {
    int i = blockIdx.x * blockDim.x + threadIdx.x;
    if (i >= n) return;
    int c = g_deg[i];
    g_deg[i] = 0;                            // self-reset for next replay
    g_cnt[i] = (c < CAP) ? c : CAP;
    float di = rsqrtf((float)(c + 1));       // +1 self loop
    g_dinv[i] = di;
    const float4* x4 = (const float4*)x;
    float4 v0 = x4[2 * i], v1 = x4[2 * i + 1];
    g_g0[4 * i]     = make_float2(di * v0.x, di * v0.y);
    g_g0[4 * i + 1] = make_float2(di * v0.z, di * v0.w);
    g_g0[4 * i + 2] = make_float2(di * v1.x, di * v1.y);
    g_g0[4 * i + 3] = make_float2(di * v1.z, di * v1.w);
}

// ---------------------------------------------------------------------------
// Fused layer 1 (R6 structure + int4 idx loads): 4 lanes/node; lane owns 2
// features; shfl(width=4) reassembles; lane emits 16 of 64 outputs (bf16).
__global__ void __launch_bounds__(256)
k_agg1_gemm1(const float* __restrict__ W1, const float* __restrict__ b1, int n) {
    __shared__ float W1s[8 * 64];
    __shared__ float b1s[64];
    int tid = threadIdx.x;
    for (int t = tid; t < 512; t += blockDim.x) W1s[t] = W1[t];
    if (tid < 64) b1s[tid] = b1[tid];
    __syncthreads();

    int gtid = blockIdx.x * blockDim.x + tid;
    int node = gtid >> 2;
    int sub  = gtid & 3;
    if (node >= n) return;

    float2 acc0 = g_g0[4 * node + sub];      // self loop
    float2 acc1 = make_float2(0.f, 0.f);
    int cnt = g_cnt[node];
    const int* col = &g_colb[node * CAP];    // bucket base: 16B aligned
    int j = 0;
    for (; j + 4 <= cnt; j += 4) {
        int4 ii = *reinterpret_cast<const int4*>(&col[j]);  // aligned, bcast
        float2 v0 = g_g0[4 * ii.x + sub];
        float2 v1 = g_g0[4 * ii.y + sub];
        float2 v2 = g_g0[4 * ii.z + sub];
        float2 v3 = g_g0[4 * ii.w + sub];
        acc0.x += v0.x; acc0.y += v0.y;
        acc1.x += v1.x; acc1.y += v1.y;
        acc0.x += v2.x; acc0.y += v2.y;
        acc1.x += v3.x; acc1.y += v3.y;
    }
    for (; j < cnt; j++) {
        int s = col[j];
        float2 v = g_g0[4 * s + sub];
        acc0.x += v.x; acc0.y += v.y;
    }
    float di = g_dinv[node];
    float mx = di * (acc0.x + acc1.x);
    float my = di * (acc0.y + acc1.y);

    float a[8];
#pragma unroll
    for (int g = 0; g < 4; g++) {
        a[2 * g]     = __shfl_sync(0xffffffffu, mx, g, 4);
        a[2 * g + 1] = __shfl_sync(0xffffffffu, my, g, 4);
    }

    int cbase = sub * 16;
    float r[16];
#pragma unroll
    for (int c = 0; c < 16; c++) r[c] = b1s[cbase + c];
#pragma unroll
    for (int k = 0; k < 8; k++) {
        float ak = a[k];
        const float* wr = &W1s[k * 64 + cbase];
#pragma unroll
        for (int c = 0; c < 16; c++) r[c] += ak * wr[c];
    }
    __nv_bfloat162 ob[8];
#pragma unroll
    for (int t = 0; t < 8; t++)
        ob[t] = __float22bfloat162_rn(make_float2(di * fmaxf(r[2 * t], 0.f),
                                                  di * fmaxf(r[2 * t + 1], 0.f)));
    uint4* dst = (uint4*)&g_g1b[node * 32 + sub * 8];
    dst[0] = *reinterpret_cast<uint4*>(&ob[0]);
    dst[1] = *reinterpret_cast<uint4*>(&ob[4]);
}

// ---------------------------------------------------------------------------
// agg2: warp/node. bf16 rows (1 L1 line/edge), packed add.rn.bf16x2, and
// int4 uniform index loads (aligned by bucket layout -> no prologue).
__global__ void k_agg2(int n) {
    int gtid = blockIdx.x * blockDim.x + threadIdx.x;
    int node = gtid >> 5;
    int lane = gtid & 31;
    if (node >= n) return;
    const uint32_t* g1 = (const uint32_t*)g_g1b;
    uint32_t acc0 = g1[(size_t)node * 32 + lane];    // self loop (raw bf16x2)
    uint32_t acc1 = 0u, acc2 = 0u, acc3 = 0u;        // bf16x2 {+0,+0}
    int cnt = g_cnt[node];
    const int* col = &g_colb[node * CAP];            // 16B aligned
    int j = 0;
    for (; j + 8 <= cnt; j += 8) {
        int4 ia = *reinterpret_cast<const int4*>(&col[j]);
        int4 ib = *reinterpret_cast<const int4*>(&col[j + 4]);
        uint32_t v0 = g1[(size_t)ia.x * 32 + lane];
        uint32_t v1 = g1[(size_t)ia.y * 32 + lane];
        uint32_t v2 = g1[(size_t)ia.z * 32 + lane];
        uint32_t v3 = g1[(size_t)ia.w * 32 + lane];
        uint32_t v4 = g1[(size_t)ib.x * 32 + lane];
        uint32_t v5 = g1[(size_t)ib.y * 32 + lane];
        uint32_t v6 = g1[(size_t)ib.z * 32 + lane];
        uint32_t v7 = g1[(size_t)ib.w * 32 + lane];
        asm("add.rn.bf16x2 %0, %0, %1;" : "+r"(acc0) : "r"(v0));
        asm("add.rn.bf16x2 %0, %0, %1;" : "+r"(acc1) : "r"(v1));
        asm("add.rn.bf16x2 %0, %0, %1;" : "+r"(acc2) : "r"(v2));
        asm("add.rn.bf16x2 %0, %0, %1;" : "+r"(acc3) : "r"(v3));
        asm("add.rn.bf16x2 %0, %0, %1;" : "+r"(acc0) : "r"(v4));
        asm("add.rn.bf16x2 %0, %0, %1;" : "+r"(acc1) : "r"(v5));
        asm("add.rn.bf16x2 %0, %0, %1;" : "+r"(acc2) : "r"(v6));
        asm("add.rn.bf16x2 %0, %0, %1;" : "+r"(acc3) : "r"(v7));
    }
    if (j + 4 <= cnt) {
        int4 ia = *reinterpret_cast<const int4*>(&col[j]);
        uint32_t v0 = g1[(size_t)ia.x * 32 + lane];
        uint32_t v1 = g1[(size_t)ia.y * 32 + lane];
        uint32_t v2 = g1[(size_t)ia.z * 32 + lane];
        uint32_t v3 = g1[(size_t)ia.w * 32 + lane];
        asm("add.rn.bf16x2 %0, %0, %1;" : "+r"(acc0) : "r"(v0));
        asm("add.rn.bf16x2 %0, %0, %1;" : "+r"(acc1) : "r"(v1));
        asm("add.rn.bf16x2 %0, %0, %1;" : "+r"(acc2) : "r"(v2));
        asm("add.rn.bf16x2 %0, %0, %1;" : "+r"(acc3) : "r"(v3));
        j += 4;
    }
    for (; j < cnt; j++) {
        int s = col[j];
        uint32_t v = g1[(size_t)s * 32 + lane];
        asm("add.rn.bf16x2 %0, %0, %1;" : "+r"(acc0) : "r"(v));
    }
    // combine chains in fp32 (precise), scale by dinv, store fp32 a2
    float2 f0 = __bfloat1622float2(*reinterpret_cast<__nv_bfloat162*>(&acc0));
    float2 f1 = __bfloat1622float2(*reinterpret_cast<__nv_bfloat162*>(&acc1));
    float2 f2 = __bfloat1622float2(*reinterpret_cast<__nv_bfloat162*>(&acc2));
    float2 f3 = __bfloat1622float2(*reinterpret_cast<__nv_bfloat162*>(&acc3));
    float di = g_dinv[node];
    ((float2*)g_a2)[node * 32 + lane] =
        make_float2(di * ((f0.x + f1.x) + (f2.x + f3.x)),
                    di * ((f0.y + f1.y) + (f2.y + f3.y)));
}

// ---------------------------------------------------------------------------
// gemm2 + relu + Wfc dot + block reduction + fused final output (ticket).
__global__ void __launch_bounds__(256)
k_gemm2_reduce(const float* __restrict__ W2, const float* __restrict__ b2,
               const float* __restrict__ Wfc, const float* __restrict__ bfc,
               float* __restrict__ out, float invn, int n) {
    __shared__ float W2s[64 * 128];
    __shared__ float b2s[128];
    __shared__ float wfs[128];
    __shared__ float red[256];
    int tid = threadIdx.x;
    for (int t = tid; t < 2048; t += blockDim.x)
        ((float4*)W2s)[t] = ((const float4*)W2)[t];
    if (tid < 128) { b2s[tid] = b2[tid]; wfs[tid] = Wfc[tid]; }
    __syncthreads();

    int i = blockIdx.x * blockDim.x + tid;
    float nodesum = 0.0f;
    if (i < n) {
        float a[64];
        const float4* ar = &g_a2[i * 16];
#pragma unroll
        for (int t = 0; t < 16; t++) {
            float4 v = ar[t];
            a[4 * t] = v.x; a[4 * t + 1] = v.y; a[4 * t + 2] = v.z; a[4 * t + 3] = v.w;
        }
        for (int ch = 0; ch < 4; ch++) {
            unsigned long long acc[16];
#pragma unroll
            for (int t = 0; t < 16; t++) acc[t] = 0ull;
#pragma unroll
            for (int k = 0; k < 64; k++) {
                unsigned int au = __float_as_uint(a[k]);
                unsigned long long ap;
                asm("mov.b64 %0, {%1, %1};" : "=l"(ap) : "r"(au));
                const ulonglong2* w =
                    reinterpret_cast<const ulonglong2*>(&W2s[k * 128 + ch * 32]);
#pragma unroll
                for (int t = 0; t < 8; t++) {
                    ulonglong2 wv = w[t];
                    asm("fma.rn.f32x2 %0, %1, %2, %0;"
                        : "+l"(acc[2 * t]) : "l"(ap), "l"(wv.x));
                    asm("fma.rn.f32x2 %0, %1, %2, %0;"
                        : "+l"(acc[2 * t + 1]) : "l"(ap), "l"(wv.y));
                }
            }
#pragma unroll
            for (int u = 0; u < 16; u++) {
                unsigned int lo_u, hi_u;
                asm("mov.b64 {%0, %1}, %2;" : "=r"(lo_u), "=r"(hi_u) : "l"(acc[u]));
                int c = ch * 32 + 2 * u;
                float v0 = fmaxf(__uint_as_float(lo_u) + b2s[c], 0.0f);
                float v1 = fmaxf(__uint_as_float(hi_u) + b2s[c + 1], 0.0f);
                nodesum += v0 * wfs[c] + v1 * wfs[c + 1];
            }
        }
    }
    red[tid] = nodesum;
    __syncthreads();
    for (int off = 128; off > 0; off >>= 1) {
        if (tid < off) red[tid] += red[tid + off];
        __syncthreads();
    }
    if (tid == 0) {
        atomicAdd(&g_total, red[0]);
        __threadfence();
        int ticket = atomicAdd(&g_done, 1);
        if (ticket == (int)gridDim.x - 1) {           // last block finalizes
            float tot = atomicExch(&g_total, 0.0f);   // read + self-reset
            out[0] = tot * invn + bfc[0];
            g_done = 0;                               // self-reset
        }
    }
}

// ---------------------------------------------------------------------------
extern "C" void kernel_launch(void* const* d_in, const int* in_sizes, int n_in,
                              void* d_out, int out_size) {
    const float* x   = (const float*)d_in[0];
    const int*   ei  = (const int*)  d_in[1];
    const float* W1  = (const float*)d_in[2];
    const float* b1  = (const float*)d_in[3];
    const float* W2  = (const float*)d_in[4];
    const float* b2  = (const float*)d_in[5];
    const float* Wfc = (const float*)d_in[6];
    const float* bfc = (const float*)d_in[7];

    int n = in_sizes[0] / 8;
    int E = in_sizes[1] / 2;
    if (n > N_MAX) n = N_MAX;
    if (E > E_MAX) E = E_MAX;

    int nb = (n + 255) / 256;
    int eb = (E + 255) / 256;
    int qb = (n * 4 + 255) / 256;    // 4 lanes per node (agg1)
    int wb = (n * 32 + 255) / 256;   // warp per node (agg2)

    k_build       <<<eb, 256>>>(ei, E);      // launch 0
    k_dinv_g0     <<<nb, 256>>>(x, n);       // launch 1
    k_agg1_gemm1  <<<qb, 256>>>(W1, b1, n);  // launch 2
    k_agg2        <<<wb, 256>>>(n);          // launch 3  <- profiled slot
    k_gemm2_reduce<<<nb, 256>>>(W2, b2, Wfc, bfc, (float*)d_out,
                                1.0f / (float)n, n);
}